// round 11
// baseline (speedup 1.0000x reference)
#include <cuda_runtime.h>
#include <cuda_fp16.h>
#include <mma.h>
#include <cstdint>

using namespace nvcuda;

constexpr int E_   = 12;
constexpr int T_   = 2048;
constexpr int H_   = 64;
constexpr int IN_  = 128;
constexpr int K3H  = 192;
constexpr int ITERS = 10;
constexpr int KTOT = E_*H_ + H_;    // 832

// ---------------------------------------------------------------------------
// Device scratch (hi/lo fp16 split representations)
// ---------------------------------------------------------------------------
__device__ __half g_eh[(size_t)E_*T_*T_];   // edge hi  [e][s][t]
__device__ __half g_el[(size_t)E_*T_*T_];   // edge lo  [e][s][t]
__device__ __half g_hh[T_*H_],  g_hl[T_*H_];    // hidden hi/lo  [s][h]
__device__ float  g_actf[2][(size_t)E_*T_*H_];  // split-K partial outputs
__device__ __half g_Bh[KTOT*K3H], g_Bl[KTOT*K3H];
__device__ float  g_iw[T_*K3H];
__device__ float  g_hbuf[2][T_*H_];

// ---------------------------------------------------------------------------
// Helpers
// ---------------------------------------------------------------------------
__device__ __forceinline__ void cp16(void* s, const void* g) {
    unsigned sa = (unsigned)__cvta_generic_to_shared(s);
    asm volatile("cp.async.ca.shared.global [%0], [%1], 16;\n" :: "r"(sa), "l"(g));
}
__device__ __forceinline__ void cp_commit() { asm volatile("cp.async.commit_group;\n"); }

// ---------------------------------------------------------------------------
// Pre-pass
// ---------------------------------------------------------------------------
__global__ void p1_conv_edge(const float* __restrict__ e) {
    size_t i = (size_t)blockIdx.x * blockDim.x + threadIdx.x;   // one float4 each
    float4 v = reinterpret_cast<const float4*>(e)[i];
    __half hx = __float2half_rn(v.x), hy = __float2half_rn(v.y);
    __half hz = __float2half_rn(v.z), hw = __float2half_rn(v.w);
    __half2* dh = reinterpret_cast<__half2*>(g_eh);
    __half2* dl = reinterpret_cast<__half2*>(g_el);
    dh[2*i]   = __halves2half2(hx, hy);
    dh[2*i+1] = __halves2half2(hz, hw);
    dl[2*i]   = __floats2half2_rn(v.x - __half2float(hx), v.y - __half2float(hy));
    dl[2*i+1] = __floats2half2_rn(v.z - __half2float(hz), v.w - __half2float(hw));
}

__global__ void p2_build_b(const float* __restrict__ w, const float* __restrict__ uzr) {
    int i = blockIdx.x * blockDim.x + threadIdx.x;
    if (i >= KTOT * K3H) return;
    int k = i / K3H, n = i % K3H;
    float v;
    if (k < E_*H_) v = w[i];
    else { int j = k - E_*H_; v = (n < 2*H_) ? uzr[j*2*H_ + n] : 0.0f; }
    __half hi = __float2half_rn(v);
    g_Bh[i] = hi;
    g_Bl[i] = __float2half_rn(v - __half2float(hi));
}

__global__ void p4_h16(const float* __restrict__ h) {
    int i = blockIdx.x * blockDim.x + threadIdx.x;
    float v = h[i];
    __half hi = __float2half_rn(v);
    g_hh[i] = hi;
    g_hl[i] = __float2half_rn(v - __half2float(hi));
}

__global__ void p3_iw(const float* __restrict__ x, const float* __restrict__ wi,
                      const float* __restrict__ bw) {
    __shared__ float xs[IN_];
    int t = blockIdx.x;
    if (threadIdx.x < IN_) xs[threadIdx.x] = x[t*IN_ + threadIdx.x];
    __syncthreads();
    int n = threadIdx.x;
    float acc = bw[n];
    #pragma unroll 8
    for (int k = 0; k < IN_; k++) acc += xs[k] * wi[k*K3H + n];
    g_iw[t*K3H + n] = acc;
}

// ---------------------------------------------------------------------------
// K1: partial act (split-K=2): C = edge^T @ h, 3-term hi/lo.  (R8 body — best)
// ---------------------------------------------------------------------------
constexpr int K1_LDA = 136;                   // 128 + 8 pad (halves)
constexpr int K1_LDB = 72;                    // 64 + 8 pad
constexpr int K1_APL = 32 * K1_LDA;           // halves per A plane per stage
constexpr int K1_BPL = 32 * K1_LDB;
constexpr int K1_STAGE = 2*K1_APL + 2*K1_BPL; // halves per stage
constexpr int K1_SMEM = 2 * K1_STAGE * 2;     // bytes = 53248
constexpr int K1_LDC = 68;                    // fp32 epilogue pitch
constexpr int K1_LDD = 66;                    // fp16 epilogue pitch

__global__ __launch_bounds__(128, 3) void k1_act() {
    extern __shared__ __half sm[];

    const int e      = blockIdx.y;
    const int m0     = blockIdx.x * 128;
    const int k_base = blockIdx.z * 1024;     // split-K half

    const int tid  = threadIdx.x;
    const int warp = tid >> 5;
    const int wm = (warp & 1) * 64;           // 2 warps along m
    const int wn = (warp >> 1) * 32;          // 2 warps along n

    const __half* Agh = g_eh + (size_t)e * T_ * T_;
    const __half* Agl = g_el + (size_t)e * T_ * T_;

    wmma::fragment<wmma::accumulator, 16,16,16, float>  accM[4][2];
    wmma::fragment<wmma::accumulator, 16,16,16, __half> accX[4][2];
    #pragma unroll
    for (int i = 0; i < 4; i++)
        #pragma unroll
        for (int j = 0; j < 2; j++) {
            wmma::fill_fragment(accM[i][j], 0.0f);
            wmma::fill_fragment(accX[i][j], __float2half(0.0f));
        }

    auto load_stage = [&](int kb) {
        __half* base = sm + (kb & 1) * K1_STAGE;
        __half* Ah = base;
        __half* Al = base + K1_APL;
        __half* Bh = base + 2*K1_APL;
        __half* Bl = base + 2*K1_APL + K1_BPL;
        const int k0 = k_base + kb * 32;
        #pragma unroll
        for (int i = 0; i < 4; i++) {             // A: 512 chunks/plane
            int c = tid + i * 128;
            int r = c >> 4, mc = (c & 15) * 8;
            const size_t go = (size_t)(k0 + r) * T_ + m0 + mc;
            cp16(Ah + r*K1_LDA + mc, Agh + go);
            cp16(Al + r*K1_LDA + mc, Agl + go);
        }
        #pragma unroll
        for (int i = 0; i < 2; i++) {             // B: 256 chunks/plane
            int c = tid + i * 128;
            int r = c >> 3, nc = (c & 7) * 8;
            const size_t go = (size_t)(k0 + r) * H_ + nc;
            cp16(Bh + r*K1_LDB + nc, g_hh + go);
            cp16(Bl + r*K1_LDB + nc, g_hl + go);
        }
        cp_commit();
    };

    load_stage(0);
    for (int kb = 0; kb < 32; kb++) {
        asm volatile("cp.async.wait_group 0;\n" ::: "memory");
        __syncthreads();
        if (kb < 31) load_stage(kb + 1);          // overlaps compute below

        const __half* base = sm + (kb & 1) * K1_STAGE;
        const __half* Ah = base;
        const __half* Al = base + K1_APL;
        const __half* Bh = base + 2*K1_APL;
        const __half* Bl = base + 2*K1_APL + K1_BPL;

        #pragma unroll
        for (int kk = 0; kk < 32; kk += 16) {
            wmma::fragment<wmma::matrix_b, 16,16,16, __half, wmma::row_major> bfh[2], bfl[2];
            #pragma unroll
            for (int j = 0; j < 2; j++) {
                wmma::load_matrix_sync(bfh[j], Bh + kk*K1_LDB + wn + 16*j, K1_LDB);
                wmma::load_matrix_sync(bfl[j], Bl + kk*K1_LDB + wn + 16*j, K1_LDB);
            }
            #pragma unroll
            for (int i = 0; i < 4; i++) {
                wmma::fragment<wmma::matrix_a, 16,16,16, __half, wmma::col_major> afh, afl;
                wmma::load_matrix_sync(afh, Ah + kk*K1_LDA + wm + 16*i, K1_LDA);
                wmma::load_matrix_sync(afl, Al + kk*K1_LDA + wm + 16*i, K1_LDA);
                #pragma unroll
                for (int j = 0; j < 2; j++) {
                    wmma::mma_sync(accM[i][j], afh, bfh[j], accM[i][j]);   // main
                    wmma::mma_sync(accX[i][j], afh, bfl[j], accX[i][j]);   // cross
                    wmma::mma_sync(accX[i][j], afl, bfh[j], accX[i][j]);   // cross
                }
            }
        }
        __syncthreads();
    }

    // Epilogue via smem (no cross-layout fragment aliasing):
    float*  Cs = reinterpret_cast<float*>(sm);                       // 128 x 68 fp32
    __half* Ds = reinterpret_cast<__half*>(
                     reinterpret_cast<char*>(sm) + 128*K1_LDC*4);    // 128 x 66 fp16
    #pragma unroll
    for (int i = 0; i < 4; i++)
        #pragma unroll
        for (int j = 0; j < 2; j++) {
            wmma::store_matrix_sync(Cs + (wm + 16*i)*K1_LDC + wn + 16*j, accM[i][j],
                                    K1_LDC, wmma::mem_row_major);
            wmma::store_matrix_sync(Ds + (wm + 16*i)*K1_LDD + wn + 16*j, accX[i][j],
                                    K1_LDD, wmma::mem_row_major);
        }
    __syncthreads();
    float* dst = g_actf[blockIdx.z] + ((size_t)e * T_ + m0) * H_;
    for (int idx = tid; idx < 128*64; idx += 128) {
        int r = idx >> 6, c = idx & 63;
        dst[(size_t)r * H_ + c] = Cs[r*K1_LDC + c] + __half2float(Ds[r*K1_LDD + c]);
    }
}

// ---------------------------------------------------------------------------
// k23: FUSED kconv + K2 + K3.
// Tile 16m x 192n per CTA (128 CTAs), 4 warps (warp tile 16 x 48).
//   A (act/h) built in-kernel from g_actf[0]+g_actf[1]+ba -> hi/lo fp16 smem
//   B (weights) cp.async 2-stage from g_Bh/g_Bl
//   awzrh tile kept in smem; K3 gates applied inline; writes h_out + planes.
// ---------------------------------------------------------------------------
constexpr int B_LDN   = 200;                  // B tile row pitch (halves)
constexpr int B_STG_H = 64 * B_LDN;           // halves per B plane per stage
constexpr int A_LD    = 72;                   // A tile pitch
constexpr int A_STG_H = 16 * A_LD;            // halves per A plane per stage
constexpr int A_OFF   = 4 * B_STG_H;          // A region after B stages
constexpr int K23_SMEM = (4*B_STG_H + 4*A_STG_H) * 2;   // 111616 B
// Epilogue layout (reuses B region from offset 0):
constexpr int CP = 196;                        // awzrh fp32 pitch
constexpr int DP = 194;                        // awzrh fp16 pitch

__global__ __launch_bounds__(128) void k23_fused(
        int it, const float* __restrict__ hidden0, float* __restrict__ dout,
        const float* __restrict__ uh, const float* __restrict__ ba) {
    extern __shared__ __half sm[];

    const int m0  = blockIdx.x * 16;
    const int tid = threadIdx.x;
    const int warp = tid >> 5;
    const int n0w = warp * 48;
    const float* h_in  = (it == 0) ? hidden0 : g_hbuf[(it - 1) & 1];
    float*       h_out = (it == ITERS - 1) ? dout : g_hbuf[it & 1];

    wmma::fragment<wmma::accumulator, 16,16,16, float>  accM[3];
    wmma::fragment<wmma::accumulator, 16,16,16, __half> accX[3];
    #pragma unroll
    for (int c = 0; c < 3; c++) {
        wmma::fill_fragment(accM[c], 0.0f);
        wmma::fill_fragment(accX[c], __float2half(0.0f));
    }

    // ---- B loader: 64k x 192n, 2 planes, cp.async ----
    auto ldB = [&](int kb) {
        __half* Bh_s = sm + (kb & 1) * 2 * B_STG_H;
        __half* Bl_s = Bh_s + B_STG_H;
        const __half* srcH = g_Bh + (size_t)kb * 64 * K3H;
        const __half* srcL = g_Bl + (size_t)kb * 64 * K3H;
        #pragma unroll
        for (int i = 0; i < 12; i++) {            // 1536 chunks / 128 thr
            int c = tid + i * 128;
            int row = c / 24, col = (c % 24) * 8;
            cp16(Bh_s + row*B_LDN + col, srcH + row*K3H + col);
            cp16(Bl_s + row*B_LDN + col, srcL + row*K3H + col);
        }
        cp_commit();
    };

    // ---- A prefetch (registers) + store-to-smem with hi/lo split ----
    const int ar = tid >> 3;                  // row 0..15
    const int ac = (tid & 7) * 8;             // col 0..56
    float4 pa0[2], pa1[2];
    auto ldA_regs = [&](int kb) {
        if (kb >= 12) return;                 // kb==12 handled directly in stA
        const size_t go = ((size_t)kb * T_ + m0 + ar) * H_ + ac;
        pa0[0] = *reinterpret_cast<const float4*>(g_actf[0] + go);
        pa0[1] = *reinterpret_cast<const float4*>(g_actf[0] + go + 4);
        pa1[0] = *reinterpret_cast<const float4*>(g_actf[1] + go);
        pa1[1] = *reinterpret_cast<const float4*>(g_actf[1] + go + 4);
    };
    auto stA = [&](int kb) {
        __half* Ah_s = sm + A_OFF + (kb & 1) * 2 * A_STG_H;
        __half* Al_s = Ah_s + A_STG_H;
        if (kb < 12) {
            float v[8];
            v[0]=pa0[0].x+pa1[0].x; v[1]=pa0[0].y+pa1[0].y;
            v[2]=pa0[0].z+pa1[0].z; v[3]=pa0[0].w+pa1[0].w;
            v[4]=pa0[1].x+pa1[1].x; v[5]=pa0[1].y+pa1[1].y;
            v[6]=pa0[1].z+pa1[1].z; v[7]=pa0[1].w+pa1[1].w;
            __half hs[8], ls[8];
            #pragma unroll
            for (int q = 0; q < 8; q++) {
                float t = v[q] + __ldg(&ba[kb*H_ + ac + q]);
                hs[q] = __float2half_rn(t);
                ls[q] = __float2half_rn(t - __half2float(hs[q]));
            }
            *reinterpret_cast<uint4*>(Ah_s + ar*A_LD + ac) = *reinterpret_cast<uint4*>(hs);
            *reinterpret_cast<uint4*>(Al_s + ar*A_LD + ac) = *reinterpret_cast<uint4*>(ls);
        } else {
            const size_t go = (size_t)(m0 + ar) * H_ + ac;
            *reinterpret_cast<uint4*>(Ah_s + ar*A_LD + ac) =
                *reinterpret_cast<const uint4*>(g_hh + go);
            *reinterpret_cast<uint4*>(Al_s + ar*A_LD + ac) =
                *reinterpret_cast<const uint4*>(g_hl + go);
        }
    };

    ldB(0);
    ldA_regs(0);

    for (int kb = 0; kb < 13; kb++) {
        if (kb + 1 < 13) ldB(kb + 1);
        if (kb + 1 < 13) asm volatile("cp.async.wait_group 1;\n" ::: "memory");
        else             asm volatile("cp.async.wait_group 0;\n" ::: "memory");
        __syncthreads();                       // B(kb) visible; A stage free
        stA(kb);
        ldA_regs(kb + 1);
        __syncthreads();                       // A(kb) visible

        const __half* Bh_s = sm + (kb & 1) * 2 * B_STG_H;
        const __half* Bl_s = Bh_s + B_STG_H;
        const __half* Ah_s = sm + A_OFF + (kb & 1) * 2 * A_STG_H;
        const __half* Al_s = Ah_s + A_STG_H;

        #pragma unroll
        for (int kk = 0; kk < 64; kk += 16) {
            wmma::fragment<wmma::matrix_a, 16,16,16, __half, wmma::row_major> afh, afl;
            wmma::load_matrix_sync(afh, Ah_s + kk, A_LD);
            wmma::load_matrix_sync(afl, Al_s + kk, A_LD);
            #pragma unroll
            for (int c = 0; c < 3; c++) {
                wmma::fragment<wmma::matrix_b, 16,16,16, __half, wmma::row_major> bfh, bfl;
                wmma::load_matrix_sync(bfh, Bh_s + kk*B_LDN + n0w + 16*c, B_LDN);
                wmma::load_matrix_sync(bfl, Bl_s + kk*B_LDN + n0w + 16*c, B_LDN);
                wmma::mma_sync(accM[c], afh, bfh, accM[c]);
                wmma::mma_sync(accX[c], afh, bfl, accX[c]);
                wmma::mma_sync(accX[c], afl, bfh, accX[c]);
            }
        }
        __syncthreads();                       // all reads done before next stA/B reuse
    }

    // ---- epilogue: awzrh tile -> smem, then K3 gates inline ----
    float*  Cs = reinterpret_cast<float*>(sm);                          // 16 x CP fp32
    __half* Ds = reinterpret_cast<__half*>(
                     reinterpret_cast<char*>(sm) + 16*CP*4);            // 16 x DP fp16
    float* uh_s = reinterpret_cast<float*>(
                     reinterpret_cast<char*>(sm) + 16*CP*4 + 16*DP*2 + 8);
    float* rh_s = uh_s + 64*65;                                          // 16 x 65

    #pragma unroll
    for (int c = 0; c < 3; c++) {
        wmma::store_matrix_sync(Cs + n0w + 16*c, accM[c], CP, wmma::mem_row_major);
        wmma::store_matrix_sync(Ds + n0w + 16*c, accX[c], DP, wmma::mem_row_major);
    }
    // load uh while awzrh stores land
    for (int i = tid; i < 64*64; i += 128)
        uh_s[(i >> 6)*65 + (i & 63)] = uh[i];
    __syncthreads();

    // r gate + r*h
    for (int i = tid; i < 16*64; i += 128) {
        int t = i >> 6, j = i & 63;
        int gt = m0 + t;
        float awr = Cs[t*CP + H_ + j] + __half2float(Ds[t*DP + H_ + j])
                  + g_iw[gt*K3H + H_ + j];
        float r = 1.0f / (1.0f + expf(-awr));
        rh_s[t*65 + j] = r * h_in[gt*H_ + j];
    }
    __syncthreads();

    const int t  = tid >> 3;                  // 16 rows, 8 threads/row
    const int nb = (tid & 7) * 8;             // 8 cols per thread
    const int gt = m0 + t;

    float acc[8];
    #pragma unroll
    for (int q = 0; q < 8; q++) {
        int n = nb + q;
        acc[q] = Cs[t*CP + 2*H_ + n] + __half2float(Ds[t*DP + 2*H_ + n])
               + g_iw[gt*K3H + 2*H_ + n];
    }
    #pragma unroll 4
    for (int j = 0; j < 64; j++) {
        float rv = rh_s[t*65 + j];
        #pragma unroll
        for (int q = 0; q < 8; q++) acc[q] += rv * uh_s[j*65 + nb + q];
    }
    #pragma unroll
    for (int q = 0; q < 8; q++) {
        int n = nb + q;
        float awz = Cs[t*CP + n] + __half2float(Ds[t*DP + n]) + g_iw[gt*K3H + n];
        float z  = 1.0f / (1.0f + expf(-awz));
        float hv = h_in[gt*H_ + n];
        float ht = tanhf(acc[q]);
        float o  = (1.0f - z) * hv + z * ht;
        h_out[gt*H_ + n] = o;
        __half hi = __float2half_rn(o);
        g_hh[gt*H_ + n] = hi;
        g_hl[gt*H_ + n] = __float2half_rn(o - __half2float(hi));
    }
}

// ---------------------------------------------------------------------------
// Launch: k1 stays in profiling slot #4; 2 launches per iteration.
// ---------------------------------------------------------------------------
extern "C" void kernel_launch(void* const* d_in, const int* in_sizes, int n_in,
                              void* d_out, int out_size) {
    (void)in_sizes; (void)n_in; (void)out_size;
    const float* x      = (const float*)d_in[0];
    const float* hidden = (const float*)d_in[1];
    const float* edge   = (const float*)d_in[2];
    const float* ba     = (const float*)d_in[3];
    const float* w      = (const float*)d_in[4];
    const float* uzr    = (const float*)d_in[5];
    const float* uh     = (const float*)d_in[6];
    const float* wi     = (const float*)d_in[7];
    const float* bw     = (const float*)d_in[8];
    float* out = (float*)d_out;

    cudaFuncSetAttribute(k1_act,    cudaFuncAttributeMaxDynamicSharedMemorySize, K1_SMEM);
    cudaFuncSetAttribute(k23_fused, cudaFuncAttributeMaxDynamicSharedMemorySize, K23_SMEM);

    // launches 1..3
    p1_conv_edge<<< (int)(((size_t)E_*T_*T_/4) / 256), 256 >>>(edge);
    p2_build_b  <<< (KTOT*K3H + 255) / 256, 256 >>>(w, uzr);
    p4_h16      <<< (T_*H_) / 256, 256 >>>(hidden);

    // launch 4 == k1_act  (ncu profiles this slot)
    k1_act      <<< dim3(T_/128, E_, 2), 128, K1_SMEM >>>();

    // launch 5: p3 (needed only by k23 below)
    p3_iw       <<< T_, K3H >>>(x, wi, bw);

    k23_fused   <<< T_/16, 128, K23_SMEM >>>(0, hidden, out, uh, ba);

    for (int it = 1; it < ITERS; ++it) {
        k1_act    <<< dim3(T_/128, E_, 2), 128, K1_SMEM >>>();
        k23_fused <<< T_/16, 128, K23_SMEM >>>(it, hidden, out, uh, ba);
    }
}

// round 12
// speedup vs baseline: 1.0925x; 1.0925x over previous
#include <cuda_runtime.h>
#include <cuda_fp16.h>
#include <mma.h>
#include <cstdint>

using namespace nvcuda;

constexpr int E_   = 12;
constexpr int T_   = 2048;
constexpr int H_   = 64;
constexpr int IN_  = 128;
constexpr int K3H  = 192;
constexpr int ITERS = 10;
constexpr int KTOT = E_*H_ + H_;    // 832

// ---------------------------------------------------------------------------
// Device scratch (hi/lo fp16 split representations)
// ---------------------------------------------------------------------------
__device__ __half g_eh[(size_t)E_*T_*T_];   // edge hi  [e][s][t]
__device__ __half g_el[(size_t)E_*T_*T_];   // edge lo  [e][s][t]
__device__ __half g_hh[T_*H_],  g_hl[T_*H_];    // hidden hi/lo  [s][h]
__device__ float  g_actf[2][(size_t)E_*T_*H_];  // split-K partial outputs
__device__ __half g_ah[(size_t)E_*T_*H_];   // act hi [e][t][h]
__device__ __half g_al[(size_t)E_*T_*H_];   // act lo
__device__ __half g_Bh[KTOT*K3H], g_Bl[KTOT*K3H];
__device__ float  g_iw[T_*K3H];
__device__ float  g_awzrh[T_*K3H];
__device__ float  g_hbuf[2][T_*H_];

// ---------------------------------------------------------------------------
// Helpers
// ---------------------------------------------------------------------------
__device__ __forceinline__ void cp16(void* s, const void* g) {
    unsigned sa = (unsigned)__cvta_generic_to_shared(s);
    asm volatile("cp.async.ca.shared.global [%0], [%1], 16;\n" :: "r"(sa), "l"(g));
}
__device__ __forceinline__ void cp_commit() { asm volatile("cp.async.commit_group;\n"); }

// ---------------------------------------------------------------------------
// p14: fused edge conversion (p1) + hidden conversion (p4)
// ---------------------------------------------------------------------------
constexpr int NB_EDGE = (int)(((size_t)E_*T_*T_/4) / 256);   // 49152 blocks
constexpr int NB_H    = (T_*H_) / 256;                       // 512 blocks

__global__ void p14_conv(const float* __restrict__ e, const float* __restrict__ h) {
    if (blockIdx.x < NB_EDGE) {
        size_t i = (size_t)blockIdx.x * 256 + threadIdx.x;   // one float4 each
        float4 v = reinterpret_cast<const float4*>(e)[i];
        __half hx = __float2half_rn(v.x), hy = __float2half_rn(v.y);
        __half hz = __float2half_rn(v.z), hw = __float2half_rn(v.w);
        __half2* dh = reinterpret_cast<__half2*>(g_eh);
        __half2* dl = reinterpret_cast<__half2*>(g_el);
        dh[2*i]   = __halves2half2(hx, hy);
        dh[2*i+1] = __halves2half2(hz, hw);
        dl[2*i]   = __floats2half2_rn(v.x - __half2float(hx), v.y - __half2float(hy));
        dl[2*i+1] = __floats2half2_rn(v.z - __half2float(hz), v.w - __half2float(hw));
    } else {
        int i = (blockIdx.x - NB_EDGE) * 256 + threadIdx.x;
        float v = h[i];
        __half hi = __float2half_rn(v);
        g_hh[i] = hi;
        g_hl[i] = __float2half_rn(v - __half2float(hi));
    }
}

// ---------------------------------------------------------------------------
// p3: iw = x @ input_wzrh + bw.  128 CTAs x 16 rows, wi staged via smem.
// ---------------------------------------------------------------------------
__global__ __launch_bounds__(192) void p3_iw(const float* __restrict__ x,
                                             const float* __restrict__ wi,
                                             const float* __restrict__ bw) {
    __shared__ float xs[16][128];
    __shared__ float ws[32][192];
    const int t0  = blockIdx.x * 16;
    const int tid = threadIdx.x;                  // 0..191 == output col n

    for (int i = tid; i < 16*128; i += 192)
        xs[i >> 7][i & 127] = x[(t0 + (i >> 7)) * IN_ + (i & 127)];

    float acc[16];
    float b = bw[tid];
    #pragma unroll
    for (int r = 0; r < 16; r++) acc[r] = b;

    for (int kc = 0; kc < 4; kc++) {
        __syncthreads();                          // xs ready / prior reads done
        for (int i = tid; i < 32*192; i += 192)
            ws[i / 192][i % 192] = wi[(kc*32 + i/192) * K3H + (i % 192)];
        __syncthreads();
        #pragma unroll
        for (int k = 0; k < 32; k++) {
            float w = ws[k][tid];
            #pragma unroll
            for (int r = 0; r < 16; r++) acc[r] += xs[r][kc*32 + k] * w;
        }
    }
    #pragma unroll
    for (int r = 0; r < 16; r++) g_iw[(t0 + r) * K3H + tid] = acc[r];
}

// ---------------------------------------------------------------------------
// K1: partial act (split-K=2): C = edge^T @ h, 3-term hi/lo, ALL into one
// fp32 accumulator (rate-neutral per R7; better accuracy; fewer regs).
// CTA tile 128m x 64n, 4 warps (64m x 32n), 2-stage cp.async (k=32).
// Epilogue: direct store_matrix_sync to g_actf (no smem round-trip).
// ---------------------------------------------------------------------------
constexpr int K1_LDA = 136;                   // 128 + 8 pad (halves)
constexpr int K1_LDB = 72;                    // 64 + 8 pad
constexpr int K1_APL = 32 * K1_LDA;           // halves per A plane per stage
constexpr int K1_BPL = 32 * K1_LDB;
constexpr int K1_STAGE = 2*K1_APL + 2*K1_BPL; // halves per stage
constexpr int K1_SMEM = 2 * K1_STAGE * 2;     // bytes = 53248

__global__ __launch_bounds__(128, 3) void k1_act() {
    extern __shared__ __half sm[];

    const int e      = blockIdx.y;
    const int m0     = blockIdx.x * 128;
    const int k_base = blockIdx.z * 1024;     // split-K half

    const int tid  = threadIdx.x;
    const int warp = tid >> 5;
    const int wm = (warp & 1) * 64;           // 2 warps along m
    const int wn = (warp >> 1) * 32;          // 2 warps along n

    const __half* Agh = g_eh + (size_t)e * T_ * T_;
    const __half* Agl = g_el + (size_t)e * T_ * T_;

    wmma::fragment<wmma::accumulator, 16,16,16, float> accM[4][2];
    #pragma unroll
    for (int i = 0; i < 4; i++)
        #pragma unroll
        for (int j = 0; j < 2; j++) wmma::fill_fragment(accM[i][j], 0.0f);

    auto load_stage = [&](int kb) {
        __half* base = sm + (kb & 1) * K1_STAGE;
        __half* Ah = base;
        __half* Al = base + K1_APL;
        __half* Bh = base + 2*K1_APL;
        __half* Bl = base + 2*K1_APL + K1_BPL;
        const int k0 = k_base + kb * 32;
        #pragma unroll
        for (int i = 0; i < 4; i++) {             // A: 512 chunks/plane
            int c = tid + i * 128;
            int r = c >> 4, mc = (c & 15) * 8;
            const size_t go = (size_t)(k0 + r) * T_ + m0 + mc;
            cp16(Ah + r*K1_LDA + mc, Agh + go);
            cp16(Al + r*K1_LDA + mc, Agl + go);
        }
        #pragma unroll
        for (int i = 0; i < 2; i++) {             // B: 256 chunks/plane
            int c = tid + i * 128;
            int r = c >> 3, nc = (c & 7) * 8;
            const size_t go = (size_t)(k0 + r) * H_ + nc;
            cp16(Bh + r*K1_LDB + nc, g_hh + go);
            cp16(Bl + r*K1_LDB + nc, g_hl + go);
        }
        cp_commit();
    };

    load_stage(0);
    for (int kb = 0; kb < 32; kb++) {
        asm volatile("cp.async.wait_group 0;\n" ::: "memory");
        __syncthreads();
        if (kb < 31) load_stage(kb + 1);          // overlaps compute below

        const __half* base = sm + (kb & 1) * K1_STAGE;
        const __half* Ah = base;
        const __half* Al = base + K1_APL;
        const __half* Bh = base + 2*K1_APL;
        const __half* Bl = base + 2*K1_APL + K1_BPL;

        #pragma unroll
        for (int kk = 0; kk < 32; kk += 16) {
            wmma::fragment<wmma::matrix_b, 16,16,16, __half, wmma::row_major> bfh[2], bfl[2];
            #pragma unroll
            for (int j = 0; j < 2; j++) {
                wmma::load_matrix_sync(bfh[j], Bh + kk*K1_LDB + wn + 16*j, K1_LDB);
                wmma::load_matrix_sync(bfl[j], Bl + kk*K1_LDB + wn + 16*j, K1_LDB);
            }
            #pragma unroll
            for (int i = 0; i < 4; i++) {
                wmma::fragment<wmma::matrix_a, 16,16,16, __half, wmma::col_major> afh, afl;
                wmma::load_matrix_sync(afh, Ah + kk*K1_LDA + wm + 16*i, K1_LDA);
                wmma::load_matrix_sync(afl, Al + kk*K1_LDA + wm + 16*i, K1_LDA);
                #pragma unroll
                for (int j = 0; j < 2; j++) {
                    wmma::mma_sync(accM[i][j], afh, bfh[j], accM[i][j]);   // main
                    wmma::mma_sync(accM[i][j], afh, bfl[j], accM[i][j]);   // cross
                    wmma::mma_sync(accM[i][j], afl, bfh[j], accM[i][j]);   // cross
                }
            }
        }
        __syncthreads();
    }

    // Direct epilogue to global (fp32 partials)
    float* dst = g_actf[blockIdx.z] + ((size_t)e * T_ + m0) * H_;
    #pragma unroll
    for (int i = 0; i < 4; i++)
        #pragma unroll
        for (int j = 0; j < 2; j++)
            wmma::store_matrix_sync(dst + (size_t)(wm + 16*i)*H_ + wn + 16*j,
                                    accM[i][j], H_, wmma::mem_row_major);
}

// ---------------------------------------------------------------------------
// kconv_p2: sum split-K partials + ba -> hi/lo fp16 planes (kconv), plus
// p2's B-build in extra blocks (idempotent each iteration).
// ---------------------------------------------------------------------------
constexpr int NB_KCONV = (E_*T_*H_/4) / 256;          // 6144
constexpr int NB_P2    = (KTOT*K3H + 255) / 256;      // 624

__global__ void kconv_p2(const float* __restrict__ ba, const float* __restrict__ w,
                         const float* __restrict__ uzr) {
    if (blockIdx.x < NB_KCONV) {
        size_t gid = (size_t)blockIdx.x * 256 + threadIdx.x;   // one float4
        float4 v0 = reinterpret_cast<const float4*>(g_actf[0])[gid];
        float4 v1 = reinterpret_cast<const float4*>(g_actf[1])[gid];
        size_t i4 = gid * 4;
        int e  = (int)(i4 / (T_ * H_));
        int c0 = (int)(i4 & 63);
        float x = v0.x + v1.x + ba[e*H_ + c0];
        float y = v0.y + v1.y + ba[e*H_ + c0 + 1];
        float z = v0.z + v1.z + ba[e*H_ + c0 + 2];
        float ww = v0.w + v1.w + ba[e*H_ + c0 + 3];
        __half2 h0 = __floats2half2_rn(x, y);
        __half2 h1 = __floats2half2_rn(z, ww);
        __half2 l0 = __floats2half2_rn(x - __low2float(h0), y - __high2float(h0));
        __half2 l1 = __floats2half2_rn(z - __low2float(h1), ww - __high2float(h1));
        reinterpret_cast<__half2*>(g_ah)[gid*2]   = h0;
        reinterpret_cast<__half2*>(g_ah)[gid*2+1] = h1;
        reinterpret_cast<__half2*>(g_al)[gid*2]   = l0;
        reinterpret_cast<__half2*>(g_al)[gid*2+1] = l1;
    } else {
        int i = (blockIdx.x - NB_KCONV) * 256 + threadIdx.x;
        if (i >= KTOT * K3H) return;
        int k = i / K3H, n = i % K3H;
        float v;
        if (k < E_*H_) v = w[i];
        else { int j = k - E_*H_; v = (n < 2*H_) ? uzr[j*2*H_ + n] : 0.0f; }
        __half hi = __float2half_rn(v);
        g_Bh[i] = hi;
        g_Bl[i] = __float2half_rn(v - __half2float(hi));
    }
}

// ---------------------------------------------------------------------------
// K2: awzrh = [act | h] @ [W ; uz_ur|0]  (M=2048, K=832, N=192).
// Main term fp32 acc; cross terms shared fp16 acc; combined via smem epilogue.
// ---------------------------------------------------------------------------
constexpr int LDA = 72, LDB = 72;
constexpr int STG = 64 * LDA;
constexpr int SMEM_K2 = 4 * 2 * STG * 2;
constexpr int K2_LDC = 68;
constexpr int K2_LDD = 66;

__global__ __launch_bounds__(128) void k2_awzrh() {
    extern __shared__ __half smem[];
    __half* Ah = smem;
    __half* Al = smem + 2*STG;
    __half* Bh = smem + 4*STG;
    __half* Bl = smem + 6*STG;

    const int m0 = blockIdx.x * 64;
    const int n0 = blockIdx.y * 64;
    const int tid  = threadIdx.x;
    const int warp = tid >> 5;
    const int wm = (warp & 1) * 32, wn = (warp >> 1) * 32;
    const int lr = tid >> 3;
    const int lc = (tid & 7) * 8;

    wmma::fragment<wmma::accumulator, 16,16,16, float>  accM[2][2];
    wmma::fragment<wmma::accumulator, 16,16,16, __half> accX[2][2];
    #pragma unroll
    for (int i = 0; i < 2; i++)
        #pragma unroll
        for (int j = 0; j < 2; j++) {
            wmma::fill_fragment(accM[i][j], 0.0f);
            wmma::fill_fragment(accX[i][j], __float2half(0.0f));
        }

    auto load_stage = [&](int st, int kb) {
        const __half* bah = (kb < E_) ? (g_ah + ((size_t)kb*T_ + m0)*H_) : (g_hh + (size_t)m0*H_);
        const __half* bal = (kb < E_) ? (g_al + ((size_t)kb*T_ + m0)*H_) : (g_hl + (size_t)m0*H_);
        const __half* bbh = g_Bh + (size_t)kb*64*K3H + n0;
        const __half* bbl = g_Bl + (size_t)kb*64*K3H + n0;
        #pragma unroll
        for (int t = 0; t < 4; t++) {
            int r = lr + 16*t;
            cp16(&Ah[(st*64 + r)*LDA + lc], bah + r*H_ + lc);
            cp16(&Al[(st*64 + r)*LDA + lc], bal + r*H_ + lc);
            cp16(&Bh[(st*64 + r)*LDB + lc], bbh + r*K3H + lc);
            cp16(&Bl[(st*64 + r)*LDB + lc], bbl + r*K3H + lc);
        }
        cp_commit();
    };

    load_stage(0, 0);
    int st = 0;
    for (int kb = 0; kb < 13; kb++) {
        if (kb + 1 < 13) {
            load_stage(st ^ 1, kb + 1);
            asm volatile("cp.async.wait_group 1;\n");
        } else {
            asm volatile("cp.async.wait_group 0;\n");
        }
        __syncthreads();

        const __half* As_ = &Ah[st*64*LDA];
        const __half* Al_ = &Al[st*64*LDA];
        const __half* Bs_ = &Bh[st*64*LDB];
        const __half* Bl_ = &Bl[st*64*LDB];
        #pragma unroll
        for (int kk = 0; kk < 64; kk += 16) {
            wmma::fragment<wmma::matrix_a, 16,16,16, __half, wmma::row_major> afh[2], afl[2];
            wmma::fragment<wmma::matrix_b, 16,16,16, __half, wmma::row_major> bfh[2], bfl[2];
            #pragma unroll
            for (int i = 0; i < 2; i++) {
                wmma::load_matrix_sync(afh[i], As_ + (wm + 16*i)*LDA + kk, LDA);
                wmma::load_matrix_sync(afl[i], Al_ + (wm + 16*i)*LDA + kk, LDA);
            }
            #pragma unroll
            for (int j = 0; j < 2; j++) {
                wmma::load_matrix_sync(bfh[j], Bs_ + kk*LDB + wn + 16*j, LDB);
                wmma::load_matrix_sync(bfl[j], Bl_ + kk*LDB + wn + 16*j, LDB);
            }
            #pragma unroll
            for (int i = 0; i < 2; i++)
                #pragma unroll
                for (int j = 0; j < 2; j++) {
                    wmma::mma_sync(accM[i][j], afh[i], bfh[j], accM[i][j]);
                    wmma::mma_sync(accX[i][j], afh[i], bfl[j], accX[i][j]);
                    wmma::mma_sync(accX[i][j], afl[i], bfh[j], accX[i][j]);
                }
        }
        __syncthreads();
        st ^= 1;
    }

    // Combine via smem epilogue
    float*  Cs = reinterpret_cast<float*>(smem);                      // 64 x 68 fp32
    __half* Ds = reinterpret_cast<__half*>(
                     reinterpret_cast<char*>(smem) + 64*K2_LDC*4);    // 64 x 66 fp16
    #pragma unroll
    for (int i = 0; i < 2; i++)
        #pragma unroll
        for (int j = 0; j < 2; j++) {
            wmma::store_matrix_sync(Cs + (wm + 16*i)*K2_LDC + wn + 16*j, accM[i][j],
                                    K2_LDC, wmma::mem_row_major);
            wmma::store_matrix_sync(Ds + (wm + 16*i)*K2_LDD + wn + 16*j, accX[i][j],
                                    K2_LDD, wmma::mem_row_major);
        }
    __syncthreads();
    for (int idx = tid; idx < 64*64; idx += 128) {
        int r = idx >> 6, c = idx & 63;
        g_awzrh[(size_t)(m0 + r)*K3H + n0 + c] =
            Cs[r*K2_LDC + c] + __half2float(Ds[r*K2_LDD + c]);
    }
}

// ---------------------------------------------------------------------------
// K3: gates + h_tilde + blend (fp32), emit fp32 h and hi/lo fp16 planes.
// ---------------------------------------------------------------------------
__global__ __launch_bounds__(256) void k3_update(int it, const float* __restrict__ hidden0,
                                                 float* __restrict__ dout,
                                                 const float* __restrict__ uh) {
    __shared__ float uh_s[64][65];
    __shared__ float rh_s[16][65];

    const int m0  = blockIdx.x * 16;
    const int tid = threadIdx.x;
    const float* h_in  = (it == 0) ? hidden0 : g_hbuf[(it - 1) & 1];
    float*       h_out = (it == ITERS - 1) ? dout : g_hbuf[it & 1];

    for (int i = tid; i < 64*64; i += 256) uh_s[i >> 6][i & 63] = uh[i];
    for (int i = tid; i < 16*64; i += 256) {
        int t = i >> 6, j = i & 63;
        int gt = m0 + t;
        float awr = g_awzrh[gt*K3H + H_ + j] + g_iw[gt*K3H + H_ + j];
        float r = 1.0f / (1.0f + expf(-awr));
        rh_s[t][j] = r * h_in[gt*H_ + j];
    }
    __syncthreads();

    const int t  = tid >> 4;
    const int nb = (tid & 15) << 2;
    const int gt = m0 + t;

    float acc[4];
    #pragma unroll
    for (int q = 0; q < 4; q++) {
        int n = nb + q;
        acc[q] = g_awzrh[gt*K3H + 2*H_ + n] + g_iw[gt*K3H + 2*H_ + n];
    }
    #pragma unroll 4
    for (int j = 0; j < 64; j++) {
        float rv = rh_s[t][j];
        #pragma unroll
        for (int q = 0; q < 4; q++) acc[q] += rv * uh_s[j][nb + q];
    }
    #pragma unroll
    for (int q = 0; q < 4; q++) {
        int n = nb + q;
        float awz = g_awzrh[gt*K3H + n] + g_iw[gt*K3H + n];
        float z  = 1.0f / (1.0f + expf(-awz));
        float hv = h_in[gt*H_ + n];
        float ht = tanhf(acc[q]);
        float o  = (1.0f - z) * hv + z * ht;
        h_out[gt*H_ + n] = o;
        __half hi = __float2half_rn(o);
        g_hh[gt*H_ + n] = hi;
        g_hl[gt*H_ + n] = __float2half_rn(o - __half2float(hi));
    }
}

// ---------------------------------------------------------------------------
// Launch order: p14, k1, kconv_p2, k2 (PROFILED slot 4), p3, k3, then iterate.
// ---------------------------------------------------------------------------
extern "C" void kernel_launch(void* const* d_in, const int* in_sizes, int n_in,
                              void* d_out, int out_size) {
    (void)in_sizes; (void)n_in; (void)out_size;
    const float* x      = (const float*)d_in[0];
    const float* hidden = (const float*)d_in[1];
    const float* edge   = (const float*)d_in[2];
    const float* ba     = (const float*)d_in[3];
    const float* w      = (const float*)d_in[4];
    const float* uzr    = (const float*)d_in[5];
    const float* uh     = (const float*)d_in[6];
    const float* wi     = (const float*)d_in[7];
    const float* bw     = (const float*)d_in[8];
    float* out = (float*)d_out;

    cudaFuncSetAttribute(k1_act,   cudaFuncAttributeMaxDynamicSharedMemorySize, K1_SMEM);
    cudaFuncSetAttribute(k2_awzrh, cudaFuncAttributeMaxDynamicSharedMemorySize, SMEM_K2);

    // [1] conversions  [2] k1(it0)  [3] kconv+p2  [4] k2 <- profiled
    p14_conv <<< NB_EDGE + NB_H, 256 >>>(edge, hidden);
    k1_act   <<< dim3(T_/128, E_, 2), 128, K1_SMEM >>>();
    kconv_p2 <<< NB_KCONV + NB_P2, 256 >>>(ba, w, uzr);
    k2_awzrh <<< dim3(T_/64, 3), 128, SMEM_K2 >>>();

    // [5] input projection (needed only by k3)  [6] k3(it0)
    p3_iw    <<< T_/16, 192 >>>(x, wi, bw);
    k3_update<<< T_/16, 256 >>>(0, hidden, out, uh);

    for (int it = 1; it < ITERS; ++it) {
        k1_act   <<< dim3(T_/128, E_, 2), 128, K1_SMEM >>>();
        kconv_p2 <<< NB_KCONV + NB_P2, 256 >>>(ba, w, uzr);
        k2_awzrh <<< dim3(T_/64, 3), 128, SMEM_K2 >>>();
        k3_update<<< T_/16, 256 >>>(it, hidden, out, uh);
    }
}

// round 13
// speedup vs baseline: 1.1443x; 1.0474x over previous
#include <cuda_runtime.h>
#include <cuda_fp16.h>
#include <mma.h>
#include <cstdint>

using namespace nvcuda;

constexpr int E_   = 12;
constexpr int T_   = 2048;
constexpr int H_   = 64;
constexpr int IN_  = 128;
constexpr int K3H  = 192;
constexpr int ITERS = 10;
constexpr int KTOT = E_*H_ + H_;    // 832

// ---------------------------------------------------------------------------
// Device scratch (hi/lo fp16 split representations)
// ---------------------------------------------------------------------------
__device__ __half g_eh[(size_t)E_*T_*T_];   // edge hi  [e][s][t]
__device__ __half g_el[(size_t)E_*T_*T_];   // edge lo  [e][s][t]
__device__ __half g_hh[T_*H_],  g_hl[T_*H_];    // hidden hi/lo  [s][h]
__device__ float  g_actf[2][(size_t)E_*T_*H_];  // K1 split-K partial outputs
__device__ __half g_ah[(size_t)E_*T_*H_];   // act hi [e][t][h]
__device__ __half g_al[(size_t)E_*T_*H_];   // act lo
__device__ __half g_Bh[KTOT*K3H], g_Bl[KTOT*K3H];
__device__ float  g_iw[T_*K3H];
__device__ float  g_aw2[2][T_*K3H];         // K2 split-K partial outputs
__device__ float  g_hbuf[2][T_*H_];

// ---------------------------------------------------------------------------
// Helpers
// ---------------------------------------------------------------------------
__device__ __forceinline__ void cp16(void* s, const void* g) {
    unsigned sa = (unsigned)__cvta_generic_to_shared(s);
    asm volatile("cp.async.ca.shared.global [%0], [%1], 16;\n" :: "r"(sa), "l"(g));
}
__device__ __forceinline__ void cp_commit() { asm volatile("cp.async.commit_group;\n"); }

// ---------------------------------------------------------------------------
// p14: fused edge conversion (p1) + hidden conversion (p4)
// ---------------------------------------------------------------------------
constexpr int NB_EDGE = (int)(((size_t)E_*T_*T_/4) / 256);   // 49152 blocks
constexpr int NB_H    = (T_*H_) / 256;                       // 512 blocks

__global__ void p14_conv(const float* __restrict__ e, const float* __restrict__ h) {
    if (blockIdx.x < NB_EDGE) {
        size_t i = (size_t)blockIdx.x * 256 + threadIdx.x;   // one float4 each
        float4 v = reinterpret_cast<const float4*>(e)[i];
        __half hx = __float2half_rn(v.x), hy = __float2half_rn(v.y);
        __half hz = __float2half_rn(v.z), hw = __float2half_rn(v.w);
        __half2* dh = reinterpret_cast<__half2*>(g_eh);
        __half2* dl = reinterpret_cast<__half2*>(g_el);
        dh[2*i]   = __halves2half2(hx, hy);
        dh[2*i+1] = __halves2half2(hz, hw);
        dl[2*i]   = __floats2half2_rn(v.x - __half2float(hx), v.y - __half2float(hy));
        dl[2*i+1] = __floats2half2_rn(v.z - __half2float(hz), v.w - __half2float(hw));
    } else {
        int i = (blockIdx.x - NB_EDGE) * 256 + threadIdx.x;
        float v = h[i];
        __half hi = __float2half_rn(v);
        g_hh[i] = hi;
        g_hl[i] = __float2half_rn(v - __half2float(hi));
    }
}

// ---------------------------------------------------------------------------
// p3: iw = x @ input_wzrh + bw.  128 CTAs x 16 rows, wi staged via smem.
// ---------------------------------------------------------------------------
__global__ __launch_bounds__(192) void p3_iw(const float* __restrict__ x,
                                             const float* __restrict__ wi,
                                             const float* __restrict__ bw) {
    __shared__ float xs[16][128];
    __shared__ float ws[32][192];
    const int t0  = blockIdx.x * 16;
    const int tid = threadIdx.x;                  // 0..191 == output col n

    for (int i = tid; i < 16*128; i += 192)
        xs[i >> 7][i & 127] = x[(t0 + (i >> 7)) * IN_ + (i & 127)];

    float acc[16];
    float b = bw[tid];
    #pragma unroll
    for (int r = 0; r < 16; r++) acc[r] = b;

    for (int kc = 0; kc < 4; kc++) {
        __syncthreads();                          // xs ready / prior reads done
        for (int i = tid; i < 32*192; i += 192)
            ws[i / 192][i % 192] = wi[(kc*32 + i/192) * K3H + (i % 192)];
        __syncthreads();
        #pragma unroll
        for (int k = 0; k < 32; k++) {
            float w = ws[k][tid];
            #pragma unroll
            for (int r = 0; r < 16; r++) acc[r] += xs[r][kc*32 + k] * w;
        }
    }
    #pragma unroll
    for (int r = 0; r < 16; r++) g_iw[(t0 + r) * K3H + tid] = acc[r];
}

// ---------------------------------------------------------------------------
// K1: partial act (split-K=2): C = edge^T @ h, 3-term hi/lo, single fp32 acc.
// CTA tile 128m x 64n, 4 warps (64m x 32n), 2-stage cp.async (k=32).
// ---------------------------------------------------------------------------
constexpr int K1_LDA = 136;                   // 128 + 8 pad (halves)
constexpr int K1_LDB = 72;                    // 64 + 8 pad
constexpr int K1_APL = 32 * K1_LDA;           // halves per A plane per stage
constexpr int K1_BPL = 32 * K1_LDB;
constexpr int K1_STAGE = 2*K1_APL + 2*K1_BPL; // halves per stage
constexpr int K1_SMEM = 2 * K1_STAGE * 2;     // bytes = 53248

__global__ __launch_bounds__(128, 3) void k1_act() {
    extern __shared__ __half sm[];

    const int e      = blockIdx.y;
    const int m0     = blockIdx.x * 128;
    const int k_base = blockIdx.z * 1024;     // split-K half

    const int tid  = threadIdx.x;
    const int warp = tid >> 5;
    const int wm = (warp & 1) * 64;           // 2 warps along m
    const int wn = (warp >> 1) * 32;          // 2 warps along n

    const __half* Agh = g_eh + (size_t)e * T_ * T_;
    const __half* Agl = g_el + (size_t)e * T_ * T_;

    wmma::fragment<wmma::accumulator, 16,16,16, float> accM[4][2];
    #pragma unroll
    for (int i = 0; i < 4; i++)
        #pragma unroll
        for (int j = 0; j < 2; j++) wmma::fill_fragment(accM[i][j], 0.0f);

    auto load_stage = [&](int kb) {
        __half* base = sm + (kb & 1) * K1_STAGE;
        __half* Ah = base;
        __half* Al = base + K1_APL;
        __half* Bh = base + 2*K1_APL;
        __half* Bl = base + 2*K1_APL + K1_BPL;
        const int k0 = k_base + kb * 32;
        #pragma unroll
        for (int i = 0; i < 4; i++) {             // A: 512 chunks/plane
            int c = tid + i * 128;
            int r = c >> 4, mc = (c & 15) * 8;
            const size_t go = (size_t)(k0 + r) * T_ + m0 + mc;
            cp16(Ah + r*K1_LDA + mc, Agh + go);
            cp16(Al + r*K1_LDA + mc, Agl + go);
        }
        #pragma unroll
        for (int i = 0; i < 2; i++) {             // B: 256 chunks/plane
            int c = tid + i * 128;
            int r = c >> 3, nc = (c & 7) * 8;
            const size_t go = (size_t)(k0 + r) * H_ + nc;
            cp16(Bh + r*K1_LDB + nc, g_hh + go);
            cp16(Bl + r*K1_LDB + nc, g_hl + go);
        }
        cp_commit();
    };

    load_stage(0);
    for (int kb = 0; kb < 32; kb++) {
        asm volatile("cp.async.wait_group 0;\n" ::: "memory");
        __syncthreads();
        if (kb < 31) load_stage(kb + 1);          // overlaps compute below

        const __half* base = sm + (kb & 1) * K1_STAGE;
        const __half* Ah = base;
        const __half* Al = base + K1_APL;
        const __half* Bh = base + 2*K1_APL;
        const __half* Bl = base + 2*K1_APL + K1_BPL;

        #pragma unroll
        for (int kk = 0; kk < 32; kk += 16) {
            wmma::fragment<wmma::matrix_b, 16,16,16, __half, wmma::row_major> bfh[2], bfl[2];
            #pragma unroll
            for (int j = 0; j < 2; j++) {
                wmma::load_matrix_sync(bfh[j], Bh + kk*K1_LDB + wn + 16*j, K1_LDB);
                wmma::load_matrix_sync(bfl[j], Bl + kk*K1_LDB + wn + 16*j, K1_LDB);
            }
            #pragma unroll
            for (int i = 0; i < 4; i++) {
                wmma::fragment<wmma::matrix_a, 16,16,16, __half, wmma::col_major> afh, afl;
                wmma::load_matrix_sync(afh, Ah + kk*K1_LDA + wm + 16*i, K1_LDA);
                wmma::load_matrix_sync(afl, Al + kk*K1_LDA + wm + 16*i, K1_LDA);
                #pragma unroll
                for (int j = 0; j < 2; j++) {
                    wmma::mma_sync(accM[i][j], afh, bfh[j], accM[i][j]);   // main
                    wmma::mma_sync(accM[i][j], afh, bfl[j], accM[i][j]);   // cross
                    wmma::mma_sync(accM[i][j], afl, bfh[j], accM[i][j]);   // cross
                }
            }
        }
        __syncthreads();
    }

    // Direct epilogue to global (fp32 partials)
    float* dst = g_actf[blockIdx.z] + ((size_t)e * T_ + m0) * H_;
    #pragma unroll
    for (int i = 0; i < 4; i++)
        #pragma unroll
        for (int j = 0; j < 2; j++)
            wmma::store_matrix_sync(dst + (size_t)(wm + 16*i)*H_ + wn + 16*j,
                                    accM[i][j], H_, wmma::mem_row_major);
}

// ---------------------------------------------------------------------------
// kconv_p2: sum split-K partials + ba -> hi/lo fp16 planes (kconv), plus
// p2's B-build in extra blocks (idempotent each iteration).
// ---------------------------------------------------------------------------
constexpr int NB_KCONV = (E_*T_*H_/4) / 256;          // 6144
constexpr int NB_P2    = (KTOT*K3H + 255) / 256;      // 624

__global__ void kconv_p2(const float* __restrict__ ba, const float* __restrict__ w,
                         const float* __restrict__ uzr) {
    if (blockIdx.x < NB_KCONV) {
        size_t gid = (size_t)blockIdx.x * 256 + threadIdx.x;   // one float4
        float4 v0 = reinterpret_cast<const float4*>(g_actf[0])[gid];
        float4 v1 = reinterpret_cast<const float4*>(g_actf[1])[gid];
        size_t i4 = gid * 4;
        int e  = (int)(i4 / (T_ * H_));
        int c0 = (int)(i4 & 63);
        float x = v0.x + v1.x + ba[e*H_ + c0];
        float y = v0.y + v1.y + ba[e*H_ + c0 + 1];
        float z = v0.z + v1.z + ba[e*H_ + c0 + 2];
        float ww = v0.w + v1.w + ba[e*H_ + c0 + 3];
        __half2 h0 = __floats2half2_rn(x, y);
        __half2 h1 = __floats2half2_rn(z, ww);
        __half2 l0 = __floats2half2_rn(x - __low2float(h0), y - __high2float(h0));
        __half2 l1 = __floats2half2_rn(z - __low2float(h1), ww - __high2float(h1));
        reinterpret_cast<__half2*>(g_ah)[gid*2]   = h0;
        reinterpret_cast<__half2*>(g_ah)[gid*2+1] = h1;
        reinterpret_cast<__half2*>(g_al)[gid*2]   = l0;
        reinterpret_cast<__half2*>(g_al)[gid*2+1] = l1;
    } else {
        int i = (blockIdx.x - NB_KCONV) * 256 + threadIdx.x;
        if (i >= KTOT * K3H) return;
        int k = i / K3H, n = i % K3H;
        float v;
        if (k < E_*H_) v = w[i];
        else { int j = k - E_*H_; v = (n < 2*H_) ? uzr[j*2*H_ + n] : 0.0f; }
        __half hi = __float2half_rn(v);
        g_Bh[i] = hi;
        g_Bl[i] = __float2half_rn(v - __half2float(hi));
    }
}

// ---------------------------------------------------------------------------
// K2 v2: awzrh partials = [act | h] @ [W ; uz_ur|0], split-K=2 over the 13
// k-blocks (0-6 / 7-12).  CTA tile 32m x 64n, grid (64, 3, 2) = 384 CTAs.
// All 3 hi/lo terms into one fp32 accumulator; direct store to g_aw2[z].
// ---------------------------------------------------------------------------
constexpr int K2_AL = 72;                     // A pitch (halves)
constexpr int K2_BL = 72;                     // B pitch
constexpr int K2_APL = 32 * K2_AL;            // 2304 halves per A plane/stage
constexpr int K2_BPL = 64 * K2_BL;            // 4608 halves per B plane/stage
constexpr int K2_STAGE = 2*K2_APL + 2*K2_BPL; // 13824 halves
constexpr int SMEM_K2 = 2 * K2_STAGE * 2;     // 55296 B

__global__ __launch_bounds__(128) void k2_awzrh() {
    extern __shared__ __half smem[];

    const int m0 = blockIdx.x * 32;
    const int n0 = blockIdx.y * 64;
    const int kb_lo = blockIdx.z ? 7 : 0;
    const int kb_hi = blockIdx.z ? 13 : 7;

    const int tid  = threadIdx.x;
    const int warp = tid >> 5;
    const int wm = (warp & 1) * 16, wn = (warp >> 1) * 32;

    wmma::fragment<wmma::accumulator, 16,16,16, float> acc[2];
    #pragma unroll
    for (int j = 0; j < 2; j++) wmma::fill_fragment(acc[j], 0.0f);

    auto load_stage = [&](int st, int kb) {
        __half* base = smem + st * K2_STAGE;
        __half* Ah = base;
        __half* Al = base + K2_APL;
        __half* Bh = base + 2*K2_APL;
        __half* Bl = base + 2*K2_APL + K2_BPL;
        const __half* bah = (kb < E_) ? (g_ah + ((size_t)kb*T_ + m0)*H_) : (g_hh + (size_t)m0*H_);
        const __half* bal = (kb < E_) ? (g_al + ((size_t)kb*T_ + m0)*H_) : (g_hl + (size_t)m0*H_);
        const __half* bbh = g_Bh + (size_t)kb*64*K3H + n0;
        const __half* bbl = g_Bl + (size_t)kb*64*K3H + n0;
        #pragma unroll
        for (int i = 0; i < 2; i++) {             // A: 256 chunks/plane
            int c = tid + i * 128;
            int r = c >> 3, nc = (c & 7) * 8;
            cp16(Ah + r*K2_AL + nc, bah + r*H_ + nc);
            cp16(Al + r*K2_AL + nc, bal + r*H_ + nc);
        }
        #pragma unroll
        for (int i = 0; i < 4; i++) {             // B: 512 chunks/plane
            int c = tid + i * 128;
            int r = c >> 3, nc = (c & 7) * 8;
            cp16(Bh + r*K2_BL + nc, bbh + r*K3H + nc);
            cp16(Bl + r*K2_BL + nc, bbl + r*K3H + nc);
        }
        cp_commit();
    };

    load_stage(0, kb_lo);
    int st = 0;
    for (int kb = kb_lo; kb < kb_hi; kb++) {
        if (kb + 1 < kb_hi) {
            load_stage(st ^ 1, kb + 1);
            asm volatile("cp.async.wait_group 1;\n");
        } else {
            asm volatile("cp.async.wait_group 0;\n");
        }
        __syncthreads();

        const __half* base = smem + st * K2_STAGE;
        const __half* Ah = base;
        const __half* Al = base + K2_APL;
        const __half* Bh = base + 2*K2_APL;
        const __half* Bl = base + 2*K2_APL + K2_BPL;

        #pragma unroll
        for (int kk = 0; kk < 64; kk += 16) {
            wmma::fragment<wmma::matrix_a, 16,16,16, __half, wmma::row_major> afh, afl;
            wmma::load_matrix_sync(afh, Ah + wm*K2_AL + kk, K2_AL);
            wmma::load_matrix_sync(afl, Al + wm*K2_AL + kk, K2_AL);
            #pragma unroll
            for (int j = 0; j < 2; j++) {
                wmma::fragment<wmma::matrix_b, 16,16,16, __half, wmma::row_major> bfh, bfl;
                wmma::load_matrix_sync(bfh, Bh + kk*K2_BL + wn + 16*j, K2_BL);
                wmma::load_matrix_sync(bfl, Bl + kk*K2_BL + wn + 16*j, K2_BL);
                wmma::mma_sync(acc[j], afh, bfh, acc[j]);
                wmma::mma_sync(acc[j], afh, bfl, acc[j]);
                wmma::mma_sync(acc[j], afl, bfh, acc[j]);
            }
        }
        __syncthreads();
        st ^= 1;
    }

    float* dst = g_aw2[blockIdx.z] + (size_t)(m0 + wm)*K3H + n0 + wn;
    #pragma unroll
    for (int j = 0; j < 2; j++)
        wmma::store_matrix_sync(dst + 16*j, acc[j], K3H, wmma::mem_row_major);
}

// ---------------------------------------------------------------------------
// K3: gates + h_tilde + blend (fp32); awzrh = g_aw2[0]+g_aw2[1]+g_iw.
// ---------------------------------------------------------------------------
__global__ __launch_bounds__(256) void k3_update(int it, const float* __restrict__ hidden0,
                                                 float* __restrict__ dout,
                                                 const float* __restrict__ uh) {
    __shared__ float uh_s[64][65];
    __shared__ float rh_s[16][65];

    const int m0  = blockIdx.x * 16;
    const int tid = threadIdx.x;
    const float* h_in  = (it == 0) ? hidden0 : g_hbuf[(it - 1) & 1];
    float*       h_out = (it == ITERS - 1) ? dout : g_hbuf[it & 1];

    for (int i = tid; i < 64*64; i += 256) uh_s[i >> 6][i & 63] = uh[i];
    for (int i = tid; i < 16*64; i += 256) {
        int t = i >> 6, j = i & 63;
        int gt = m0 + t;
        int o = gt*K3H + H_ + j;
        float awr = g_aw2[0][o] + g_aw2[1][o] + g_iw[o];
        float r = 1.0f / (1.0f + expf(-awr));
        rh_s[t][j] = r * h_in[gt*H_ + j];
    }
    __syncthreads();

    const int t  = tid >> 4;
    const int nb = (tid & 15) << 2;
    const int gt = m0 + t;

    float acc[4];
    #pragma unroll
    for (int q = 0; q < 4; q++) {
        int o = gt*K3H + 2*H_ + nb + q;
        acc[q] = g_aw2[0][o] + g_aw2[1][o] + g_iw[o];
    }
    #pragma unroll 4
    for (int j = 0; j < 64; j++) {
        float rv = rh_s[t][j];
        #pragma unroll
        for (int q = 0; q < 4; q++) acc[q] += rv * uh_s[j][nb + q];
    }
    #pragma unroll
    for (int q = 0; q < 4; q++) {
        int n = nb + q;
        int o = gt*K3H + n;
        float awz = g_aw2[0][o] + g_aw2[1][o] + g_iw[o];
        float z  = 1.0f / (1.0f + expf(-awz));
        float hv = h_in[gt*H_ + n];
        float ht = tanhf(acc[q]);
        float o2 = (1.0f - z) * hv + z * tanhf(acc[q]);
        (void)ht;
        h_out[gt*H_ + n] = o2;
        __half hi = __float2half_rn(o2);
        g_hh[gt*H_ + n] = hi;
        g_hl[gt*H_ + n] = __float2half_rn(o2 - __half2float(hi));
    }
}

// ---------------------------------------------------------------------------
// Launch order: p14, k1, kconv_p2, k2 (PROFILED slot 4), p3, k3, then iterate.
// ---------------------------------------------------------------------------
extern "C" void kernel_launch(void* const* d_in, const int* in_sizes, int n_in,
                              void* d_out, int out_size) {
    (void)in_sizes; (void)n_in; (void)out_size;
    const float* x      = (const float*)d_in[0];
    const float* hidden = (const float*)d_in[1];
    const float* edge   = (const float*)d_in[2];
    const float* ba     = (const float*)d_in[3];
    const float* w      = (const float*)d_in[4];
    const float* uzr    = (const float*)d_in[5];
    const float* uh     = (const float*)d_in[6];
    const float* wi     = (const float*)d_in[7];
    const float* bw     = (const float*)d_in[8];
    float* out = (float*)d_out;

    cudaFuncSetAttribute(k1_act,   cudaFuncAttributeMaxDynamicSharedMemorySize, K1_SMEM);
    cudaFuncSetAttribute(k2_awzrh, cudaFuncAttributeMaxDynamicSharedMemorySize, SMEM_K2);

    // [1] conversions  [2] k1(it0)  [3] kconv+p2  [4] k2 <- profiled
    p14_conv <<< NB_EDGE + NB_H, 256 >>>(edge, hidden);
    k1_act   <<< dim3(T_/128, E_, 2), 128, K1_SMEM >>>();
    kconv_p2 <<< NB_KCONV + NB_P2, 256 >>>(ba, w, uzr);
    k2_awzrh <<< dim3(T_/32, 3, 2), 128, SMEM_K2 >>>();

    // [5] input projection (needed only by k3)  [6] k3(it0)
    p3_iw    <<< T_/16, 192 >>>(x, wi, bw);
    k3_update<<< T_/16, 256 >>>(0, hidden, out, uh);

    for (int it = 1; it < ITERS; ++it) {
        k1_act   <<< dim3(T_/128, E_, 2), 128, K1_SMEM >>>();
        kconv_p2 <<< NB_KCONV + NB_P2, 256 >>>(ba, w, uzr);
        k2_awzrh <<< dim3(T_/32, 3, 2), 128, SMEM_K2 >>>();
        k3_update<<< T_/16, 256 >>>(it, hidden, out, uh);
    }
}